// round 12
// baseline (speedup 1.0000x reference)
#include <cuda_runtime.h>
#include <cstdint>

#define NROWS 1000000
#define H     128
#define K     64
#define TEMP  30.0f
#define TILE_M 128
#define TTOT  ((NROWS + TILE_M - 1) / TILE_M)   // 7813
#define BSTR  144    // k3 B smem row stride (LDS.128 conflict-free)
#define SSTR  132    // k1 zn-tile stride (scalar LDS conflict-free)
#define K1GRID 444   // 3 CTAs/SM x 148

// ---------------- scratch (no device mallocs allowed) ----------------
__device__ float    g_sums[K * H];
__device__ float    g_cnts[K];
__device__ uint32_t g_mu32[K * H];   // tf32-rounded mu bits

// ---------------- PTX helpers (baseline PTX only) ----------------
__device__ __forceinline__ uint32_t to_tf32(float f) {
    uint32_t u;
    asm("cvt.rna.tf32.f32 %0, %1;" : "=r"(u) : "f"(f));
    return u;
}
// m16n8k8 tf32 MMA, fp32 accum
__device__ __forceinline__ void mma_tf32(float* c, const uint32_t* a, const uint32_t* b) {
    asm volatile(
        "mma.sync.aligned.m16n8k8.row.col.f32.tf32.tf32.f32 "
        "{%0,%1,%2,%3}, {%4,%5,%6,%7}, {%8,%9}, {%0,%1,%2,%3};"
        : "+f"(c[0]), "+f"(c[1]), "+f"(c[2]), "+f"(c[3])
        : "r"(a[0]), "r"(a[1]), "r"(a[2]), "r"(a[3]), "r"(b[0]), "r"(b[1]));
}

// ---------------------------------------------------------------------------
__global__ void k_zero() {
    int i = blockIdx.x * blockDim.x + threadIdx.x;
    if (i < K * H) g_sums[i] = 0.0f;
    if (i < K)     g_cnts[i] = 0.0f;
}

// ---------------------------------------------------------------------------
// k1: normalize z -> zn AND compute per-community sums via one-hot tf32 GEMM.
//   sums[k,h] = sum_n (comm[n]==k) * zn[n,h]. Per 128-row chunk: stage zn in
//   smem, then 16 m16n8k8 K-steps/warp with B synthesized from comm compares
//   (no smem atomics at all). Block psum lives in registers across chunks,
//   flushed once via global atomicAdd. Counts: 1 smem atomic per row (64 addrs).
//   MMA fragment map (m16n8k8 tf32): A[m,k]: a0=(qr,qc) a1=(qr+8,qc)
//   a2=(qr,qc+4) a3=(qr+8,qc+4); B[k,n]: b0=(qc,qr) b1=(qc+4,qr);
//   D[m,n]: c0=(qr,2qc) c1=(qr,2qc+1) c2=(qr+8,2qc) c3=(qr+8,2qc+1).
//   Here m = h-within-16 (warp owns h [16w,16w+16)), k = row-within-8, n = community-within-8.
// ---------------------------------------------------------------------------
__global__ void __launch_bounds__(256)
k_norm_acc(const float* __restrict__ z, const int* __restrict__ comm,
           float* __restrict__ zn) {
    __shared__ float As[TILE_M * SSTR];   // 67584 B
    __shared__ int   sComm[TILE_M];
    __shared__ float sCnt[K];

    int tid  = threadIdx.x;
    int lane = tid & 31;
    int warp = tid >> 5;          // 0..7
    int qr   = lane >> 2;         // 0..7
    int qc   = lane & 3;          // 0..3

    if (tid < K) sCnt[tid] = 0.0f;

    float c[8][4];                // psum: D[h=16*warp+..][comm=8*nt+..]
    #pragma unroll
    for (int nt = 0; nt < 8; nt++)
        #pragma unroll
        for (int q = 0; q < 4; q++) c[nt][q] = 0.0f;

    const int hbase = warp * 16;

    for (int chunk = blockIdx.x; chunk < TTOT; chunk += K1GRID) {
        long rowbase = (long)chunk * TILE_M;

        __syncthreads();   // previous chunk's MMA reads of As complete

        // Phase A: warp-per-row normalize; warp w handles local rows w+8i.
        #pragma unroll 4
        for (int i = 0; i < 16; i++) {
            int  lr  = warp + i * 8;
            long row = rowbase + lr;
            bool ok  = row < NROWS;

            float4 v = make_float4(0.f, 0.f, 0.f, 0.f);
            if (ok) v = ((const float4*)(z + row * (long)H))[lane];
            float ss = v.x * v.x + v.y * v.y + v.z * v.z + v.w * v.w;
            #pragma unroll
            for (int o = 16; o; o >>= 1) ss += __shfl_xor_sync(0xffffffffu, ss, o);
            float inv = rsqrtf(fmaxf(ss, 1e-30f));
            v.x *= inv; v.y *= inv; v.z *= inv; v.w *= inv;

            if (ok) ((float4*)(zn + row * (long)H))[lane] = v;
            *(float4*)&As[lr * SSTR + lane * 4] = v;

            if (lane == 0) {
                int cm = ok ? __ldg(comm + row) : -1;
                sComm[lr] = cm;
                if (cm >= 0) atomicAdd(&sCnt[cm], 1.0f);
            }
        }
        __syncthreads();   // As + sComm visible

        // Phase B: one-hot GEMM accumulate. 16 K-steps of 8 rows.
        #pragma unroll
        for (int s = 0; s < 16; s++) {
            int rb = s * 8;
            uint32_t ua[4];
            ua[0] = to_tf32(As[(rb + qc)     * SSTR + hbase + qr]);
            ua[1] = to_tf32(As[(rb + qc)     * SSTR + hbase + qr + 8]);
            ua[2] = to_tf32(As[(rb + qc + 4) * SSTR + hbase + qr]);
            ua[3] = to_tf32(As[(rb + qc + 4) * SSTR + hbase + qr + 8]);
            int c0 = sComm[rb + qc];
            int c1 = sComm[rb + qc + 4];
            #pragma unroll
            for (int nt = 0; nt < 8; nt++) {
                int kk = nt * 8 + qr;
                uint32_t b[2];
                b[0] = (c0 == kk) ? 0x3F800000u : 0u;
                b[1] = (c1 == kk) ? 0x3F800000u : 0u;
                mma_tf32(c[nt], ua, b);
            }
        }
    }

    // Flush psum -> g_sums (layout [k*H + h]).
    #pragma unroll
    for (int nt = 0; nt < 8; nt++) {
        int k0 = nt * 8 + 2 * qc;
        atomicAdd(&g_sums[(k0)     * H + hbase + qr],     c[nt][0]);
        atomicAdd(&g_sums[(k0 + 1) * H + hbase + qr],     c[nt][1]);
        atomicAdd(&g_sums[(k0)     * H + hbase + qr + 8], c[nt][2]);
        atomicAdd(&g_sums[(k0 + 1) * H + hbase + qr + 8], c[nt][3]);
    }
    __syncthreads();
    if (tid < K) atomicAdd(&g_cnts[tid], sCnt[tid]);
}

// ---------------------------------------------------------------------------
__global__ void k_mu(float* __restrict__ mu) {
    int i = blockIdx.x * blockDim.x + threadIdx.x;
    if (i < K * H) {
        float c = g_cnts[i / H];
        float v = g_sums[i] / fmaxf(c, 1.0f);
        mu[i] = v;
        g_mu32[i] = to_tf32(v);   // pre-rounded tf32 bits for the MMA B operand
    }
}

// ---------------------------------------------------------------------------
// k3: dist = zn @ mu^T via tf32 mma.sync.m16n8k8, fused softmax -> r.
//   (unchanged from R9 — 176 us, DRAM 70%)
// ---------------------------------------------------------------------------
__global__ void __launch_bounds__(128, 4)
k_dist_mma(const float* __restrict__ zn,
           float* __restrict__ r, float* __restrict__ dist) {
    __shared__ uint32_t Bs[K * BSTR];

    int tid  = threadIdx.x;
    long base = (long)blockIdx.x * TILE_M;

    #pragma unroll
    for (int i = 0; i < 16; i++) {
        int idx = i * 128 + tid;
        int row = idx >> 5, ch = idx & 31;
        *(uint4*)&Bs[row * BSTR + ch * 4] = *(const uint4*)(g_mu32 + row * H + ch * 4);
    }
    __syncthreads();

    int lane = tid & 31, wid = tid >> 5;
    int qr = lane >> 2;
    int qc = lane & 3;

    long rowA[2], rowB[2];
    const float* aLo[2];
    const float* aHi[2];
    #pragma unroll
    for (int mt = 0; mt < 2; mt++) {
        rowA[mt] = base + wid * 32 + mt * 16 + qr;
        rowB[mt] = rowA[mt] + 8;
        long ca = rowA[mt] < NROWS ? rowA[mt] : (NROWS - 1);
        long cb = rowB[mt] < NROWS ? rowB[mt] : (NROWS - 1);
        aLo[mt] = zn + ca * (long)H + 4 * qc;
        aHi[mt] = zn + cb * (long)H + 4 * qc;
    }

    const uint32_t* bBase = Bs + qr * BSTR + 4 * qc;

    float c[2][8][4];
    #pragma unroll
    for (int mt = 0; mt < 2; mt++)
        #pragma unroll
        for (int n = 0; n < 8; n++)
            #pragma unroll
            for (int q = 0; q < 4; q++) c[mt][n][q] = 0.0f;

    #pragma unroll
    for (int u = 0; u < 8; u++) {
        int co = u * 16;
        uint32_t ua0[2][4], ua1[2][4];
        #pragma unroll
        for (int mt = 0; mt < 2; mt++) {
            float4 lo = *(const float4*)(aLo[mt] + co);
            float4 hi = *(const float4*)(aHi[mt] + co);
            ua0[mt][0] = to_tf32(lo.x); ua0[mt][1] = to_tf32(hi.x);
            ua0[mt][2] = to_tf32(lo.y); ua0[mt][3] = to_tf32(hi.y);
            ua1[mt][0] = to_tf32(lo.z); ua1[mt][1] = to_tf32(hi.z);
            ua1[mt][2] = to_tf32(lo.w); ua1[mt][3] = to_tf32(hi.w);
        }
        #pragma unroll
        for (int n = 0; n < 8; n++) {
            uint4 b4 = *(const uint4*)(bBase + n * 8 * BSTR + co);
            uint32_t ub0[2] = { b4.x, b4.y };
            uint32_t ub1[2] = { b4.z, b4.w };
            mma_tf32(c[0][n], ua0[0], ub0);
            mma_tf32(c[1][n], ua0[1], ub0);
            mma_tf32(c[0][n], ua1[0], ub1);
            mma_tf32(c[1][n], ua1[1], ub1);
        }
    }

    #pragma unroll
    for (int mt = 0; mt < 2; mt++) {
        float va[16], vb[16];
        #pragma unroll
        for (int n = 0; n < 8; n++) {
            va[2 * n] = c[mt][n][0]; va[2 * n + 1] = c[mt][n][1];
            vb[2 * n] = c[mt][n][2]; vb[2 * n + 1] = c[mt][n][3];
        }

        float mxa = va[0], mxb = vb[0];
        #pragma unroll
        for (int i = 1; i < 16; i++) {
            mxa = fmaxf(mxa, va[i]);
            mxb = fmaxf(mxb, vb[i]);
        }
        mxa = fmaxf(mxa, __shfl_xor_sync(0xffffffffu, mxa, 1));
        mxa = fmaxf(mxa, __shfl_xor_sync(0xffffffffu, mxa, 2));
        mxb = fmaxf(mxb, __shfl_xor_sync(0xffffffffu, mxb, 1));
        mxb = fmaxf(mxb, __shfl_xor_sync(0xffffffffu, mxb, 2));

        float ea[16], eb[16], sa = 0.0f, sbv = 0.0f;
        #pragma unroll
        for (int i = 0; i < 16; i++) {
            ea[i] = __expf(TEMP * (va[i] - mxa)); sa  += ea[i];
            eb[i] = __expf(TEMP * (vb[i] - mxb)); sbv += eb[i];
        }
        sa  += __shfl_xor_sync(0xffffffffu, sa, 1);
        sa  += __shfl_xor_sync(0xffffffffu, sa, 2);
        sbv += __shfl_xor_sync(0xffffffffu, sbv, 1);
        sbv += __shfl_xor_sync(0xffffffffu, sbv, 2);
        float isa = 1.0f / sa, isb = 1.0f / sbv;

        int colb = qc * 2;
        if (rowA[mt] < NROWS) {
            float* dr = dist + rowA[mt] * (long)K + colb;
            float* rr = r    + rowA[mt] * (long)K + colb;
            #pragma unroll
            for (int n = 0; n < 8; n++) {
                *(float2*)(dr + n * 8) = make_float2(va[2 * n], va[2 * n + 1]);
                *(float2*)(rr + n * 8) = make_float2(ea[2 * n] * isa, ea[2 * n + 1] * isa);
            }
        }
        if (rowB[mt] < NROWS) {
            float* dr = dist + rowB[mt] * (long)K + colb;
            float* rr = r    + rowB[mt] * (long)K + colb;
            #pragma unroll
            for (int n = 0; n < 8; n++) {
                *(float2*)(dr + n * 8) = make_float2(vb[2 * n], vb[2 * n + 1]);
                *(float2*)(rr + n * 8) = make_float2(eb[2 * n] * isb, eb[2 * n + 1] * isb);
            }
        }
    }
}

// ---------------------------------------------------------------------------
// kernel_launch: out layout = zn [N*H] | mu [K*H] | r [N*K] | dist [N*K]
// ---------------------------------------------------------------------------
extern "C" void kernel_launch(void* const* d_in, const int* in_sizes, int n_in,
                              void* d_out, int out_size) {
    const float* z    = (const float*)d_in[0];
    const int*   comm = (const int*)d_in[1];

    float* out  = (float*)d_out;
    float* zn   = out;
    float* mu   = zn + (long)NROWS * H;
    float* rr   = mu + (long)K * H;
    float* dist = rr + (long)NROWS * K;

    k_zero<<<(K * H + 255) / 256, 256>>>();
    k_norm_acc<<<K1GRID, 256>>>(z, comm, zn);
    k_mu<<<(K * H + 255) / 256, 256>>>(mu);
    k_dist_mma<<<TTOT, 128>>>(zn, rr, dist);
}